// round 1
// baseline (speedup 1.0000x reference)
#include <cuda_runtime.h>

// Problem constants (fixed by the reference)
constexpr int B_ = 8192;   // batch rows
constexpr int K_ = 32;     // negatives per row
constexpr int N_ = 33;     // 1 pos + K negs
constexpr int D_ = 129;    // hyperboloid dim (128 + time coord)
constexpr int V_ = 2048;   // tree vocab
constexpr int KTOP = 10;   // NDCG cutoff
constexpr float WEIGHT_ = 0.15f;

// Per-row loss scratch (device global: no allocations allowed)
__device__ float g_loss[B_];

__device__ __forceinline__ float warp_sum(float v) {
#pragma unroll
    for (int o = 16; o; o >>= 1) v += __shfl_xor_sync(0xffffffffu, v, o);
    return v;
}

__global__ void __launch_bounds__(256) lr_main(
    const float* __restrict__ anchor,
    const float* __restrict__ positive,
    const float* __restrict__ negative,
    const float* __restrict__ tree,
    const int*   __restrict__ aidx,
    const int*   __restrict__ pidx,
    const int*   __restrict__ nidx)
{
    __shared__ float sD[8][N_ + 1];   // distances
    __shared__ float sR[8][N_ + 1];   // t -> rel
    __shared__ float sC[8][N_ + 1];   // disc
    const int w    = threadIdx.x >> 5;
    const int lane = threadIdx.x & 31;
    const int b    = blockIdx.x * 8 + w;
    if (b >= B_) return;

    float* dS = sD[w];
    float* rS = sR[w];
    float* cS = sC[w];

    // ---- anchor registers, sign-flipped for c>=1 so that
    //      sum(ah_c * v_c) = u0*v0 - sum_{c>=1} u_c v_c = -inner ----
    const float* arow = anchor + (size_t)b * D_;
    float ah[5];
#pragma unroll
    for (int k = 0; k < 4; k++) {
        int c = lane + 32 * k;
        float a = arow[c];
        ah[k] = (c == 0) ? a : -a;
    }
    ah[4] = (lane == 0) ? -arow[128] : 0.0f;

    // ---- 33 Lorentz distances ----
    for (int t = 0; t < N_; t++) {
        const float* v = (t == 0) ? (positive + (size_t)b * D_)
                                  : (negative + ((size_t)b * K_ + (t - 1)) * (size_t)D_);
        float p = 0.0f;
#pragma unroll
        for (int k = 0; k < 4; k++) p += ah[k] * v[lane + 32 * k];
        if (lane == 0) p += ah[4] * v[128];
        p = warp_sum(p);
        if (lane == 0) {
            float x = fmaxf(p, 1.0f + 1e-7f);               // -inner, clamped
            dS[t] = logf(x + sqrtf(x * x - 1.0f));          // arccosh
        }
    }
    __syncwarp();

    // ---- tree-distance gather ----
    const int ai = aidx[b];
    for (int i = lane; i < N_; i += 32) {
        int col = (i == 0) ? pidx[b] : nidx[b * K_ + (i - 1)];
        rS[i] = tree[(size_t)ai * V_ + col];
    }
    __syncwarp();

    // ---- rel = (max_t - t + 1e-6) / (max_t + 1e-6) ----
    float maxt = -1e30f;
#pragma unroll 1
    for (int i = 0; i < N_; i++) maxt = fmaxf(maxt, rS[i]);
    __syncwarp();
    const float inv_mt = 1.0f / (maxt + 1e-6f);
    for (int i = lane; i < N_; i += 32)
        rS[i] = (maxt - rS[i] + 1e-6f) * inv_mt;
    __syncwarp();

    // ---- ranks (ascending d, stable), disc, and IDCG (descending rel, stable) ----
    float idcg_part = 0.0f;
    for (int i = lane; i < N_; i += 32) {
        const float di = dS[i], ri = rS[i];
        int rank = 1;   // 1-based ascending rank of d[i]
        int rr   = 0;   // 0-based descending rank of rel[i]
#pragma unroll 1
        for (int j = 0; j < N_; j++) {
            const float dj = dS[j], rj = rS[j];
            rank += (dj < di) || (dj == di && j < i);
            rr   += (rj > ri) || (rj == ri && j < i);
        }
        cS[i] = (rank <= KTOP) ? (1.0f / log2f((float)(rank + 1))) : 0.0f;
        if (rr < KTOP) idcg_part += ri / log2f((float)(rr + 2));
    }
    const float idcg = warp_sum(idcg_part);
    const float inv_idcg = (idcg > 0.0f) ? (1.0f / idcg) : 0.0f;
    __syncwarp();

    // ---- pairwise lambda sum: loss_b = sum_{i<j} term(i,j)
    //      (term is symmetric, diagonal zero, so 0.5*sum_all == sum_{i<j}) ----
    float acc = 0.0f;
    {
        const int i = lane;                 // i in [0,32); i=32 has no j>i
        const float di = dS[i], ri = rS[i], ci = cS[i];
#pragma unroll 1
        for (int j = i + 1; j < N_; j++) {
            const float drel  = ri - rS[j];
            const float ddisc = ci - cS[j];
            const float delta = fabsf(drel * ddisc) * inv_idcg;
            if (delta != 0.0f) {
                const float dd = dS[j] - di;           // dd[i][j] = d[j]-d[i]
                const float s  = (drel > 0.0f) ? 1.0f : -1.0f;
                const float x  = s * dd;
                const float sig = 1.0f / (1.0f + __expf(-x));
                acc += s * delta * sig * (-dd);
            }
        }
    }
    acc = warp_sum(acc);
    if (lane == 0) g_loss[b] = acc;
}

// Deterministic final reduction: mean over B, times WEIGHT
__global__ void __launch_bounds__(256) lr_reduce(float* __restrict__ out)
{
    __shared__ float s[256];
    float v = 0.0f;
    for (int i = threadIdx.x; i < B_; i += 256) v += g_loss[i];
    s[threadIdx.x] = v;
    __syncthreads();
#pragma unroll
    for (int o = 128; o; o >>= 1) {
        if (threadIdx.x < o) s[threadIdx.x] += s[threadIdx.x + o];
        __syncthreads();
    }
    if (threadIdx.x == 0) out[0] = WEIGHT_ * s[0] / (float)B_;
}

extern "C" void kernel_launch(void* const* d_in, const int* in_sizes, int n_in,
                              void* d_out, int out_size)
{
    const float* anchor   = (const float*)d_in[0];
    const float* positive = (const float*)d_in[1];
    const float* negative = (const float*)d_in[2];
    const float* tree     = (const float*)d_in[3];
    const int*   aidx     = (const int*)d_in[4];
    const int*   pidx     = (const int*)d_in[5];
    const int*   nidx     = (const int*)d_in[6];

    lr_main<<<B_ / 8, 256>>>(anchor, positive, negative, tree, aidx, pidx, nidx);
    lr_reduce<<<1, 256>>>((float*)d_out);
}

// round 2
// speedup vs baseline: 1.3704x; 1.3704x over previous
#include <cuda_runtime.h>

constexpr int B_ = 8192;   // batch rows
constexpr int K_ = 32;     // negatives per row
constexpr int D_ = 129;    // 128 + time coord
constexpr int V_ = 2048;   // tree vocab
constexpr int KTOP = 10;
constexpr float WEIGHT_ = 0.15f;
constexpr int WARPS_PER_BLK = 8;
constexpr int BLOCKS = B_ / WARPS_PER_BLK;   // 1024

// device scratch (no allocations allowed)
__device__ float g_part[BLOCKS];
__device__ int   g_count = 0;

__device__ __forceinline__ float warp_sum(float v) {
#pragma unroll
    for (int o = 16; o; o >>= 1) v += __shfl_xor_sync(0xffffffffu, v, o);
    return v;
}
__device__ __forceinline__ float warp_max(float v) {
#pragma unroll
    for (int o = 16; o; o >>= 1) v = fmaxf(v, __shfl_xor_sync(0xffffffffu, v, o));
    return v;
}
__device__ __forceinline__ float acoshd(float x) {
    x = fmaxf(x, 1.0f + 1e-7f);
    return logf(x + sqrtf(x * x - 1.0f));
}
// symmetric pair contribution: term(i,j) == term(j,i); loss_b = sum_{i<j} term
__device__ __forceinline__ float pair_term(float ri, float ci, float di,
                                           float rj, float cj, float dj,
                                           float inv_idcg) {
    float drel  = ri - rj;
    float delta = fabsf(drel * (ci - cj)) * inv_idcg;
    float dd    = dj - di;                         // dd[i][j] = d_j - d_i
    float s     = (drel > 0.0f) ? 1.0f : -1.0f;    // drel==0 -> delta==0 -> term 0
    float x     = s * dd;
    float sig   = __fdividef(1.0f, 1.0f + __expf(-x));
    return s * delta * sig * (-dd);
}

__global__ void __launch_bounds__(256) lr_fused(
    const float* __restrict__ anchor,
    const float* __restrict__ positive,
    const float* __restrict__ negative,
    const float* __restrict__ tree,
    const int*   __restrict__ aidx,
    const int*   __restrict__ pidx,
    const int*   __restrict__ nidx,
    float*       __restrict__ out)
{
    __shared__ float s_warp[WARPS_PER_BLK];
    __shared__ float s_fin[256];
    __shared__ bool  s_last;

    const int w    = threadIdx.x >> 5;
    const int lane = threadIdx.x & 31;
    const int b    = blockIdx.x * WARPS_PER_BLK + w;

    const float* __restrict__ arow = anchor   + (size_t)b * D_;
    const float* __restrict__ pb   = positive + (size_t)b * D_;
    const float* __restrict__ nb   = negative + (size_t)b * K_ * D_;

    // anchor in registers, sign-flipped for c>=1: sum(ah_c*v_c) = -inner
    const float ah0 = (lane == 0) ? arow[0] : -arow[lane];
    const float ah1 = -arow[lane + 32];
    const float ah2 = -arow[lane + 64];
    const float ah3 = -arow[lane + 96];
    const float a128n = -arow[128];               // uniform broadcast load

    // ---- phase 1: 33 independent partial dots (high MLP, no cross-lane deps) ----
    float p[33];
    {
        const float* v = pb;
        p[0] = fmaf(ah0, v[lane], fmaf(ah1, v[lane + 32],
               fmaf(ah2, v[lane + 64], ah3 * v[lane + 96])));
    }
#pragma unroll
    for (int t = 1; t < 33; t++) {
        const float* v = nb + (t - 1) * D_;
        p[t] = fmaf(ah0, v[lane], fmaf(ah1, v[lane + 32],
               fmaf(ah2, v[lane + 64], ah3 * v[lane + 96])));
    }

    // ---- phase 2: butterfly transpose-reduce: lane L ends with item L's sum ----
#pragma unroll
    for (int m = 16; m >= 1; m >>= 1) {
        const bool up = (lane & m) != 0;
#pragma unroll
        for (int t = 0; t < m; t++) {
            float send = up ? p[t] : p[t + m];
            float recv = __shfl_xor_sync(0xffffffffu, send, m);
            float keep = up ? p[t + m] : p[t];
            p[t] = keep + recv;
        }
    }
    float dsum  = p[0];                 // item `lane` (lane 0 = positive)
    float s32   = warp_sum(p[32]);      // item 32 on all lanes

    // tail component (element 128 of each row)
    const float* rowme = (lane == 0) ? pb : (nb + (lane - 1) * D_);
    dsum += a128n * rowme[128];
    s32  += a128n * nb[31 * D_ + 128];  // uniform

    const float dme = acoshd(dsum);
    const float d32 = acoshd(s32);

    // ---- tree-distance gather + rel ----
    const int ai = aidx[b];
    const float* __restrict__ trow = tree + (size_t)ai * V_;
    const int colme = (lane == 0) ? pidx[b] : nidx[b * K_ + lane - 1];
    const float tme = trow[colme];
    const float t32 = trow[nidx[b * K_ + 31]];   // uniform

    const float maxt   = fmaxf(warp_max(tme), t32);
    const float inv_mt = __fdividef(1.0f, maxt + 1e-6f);
    const float relme  = (maxt - tme + 1e-6f) * inv_mt;
    const float rel32  = (maxt - t32 + 1e-6f) * inv_mt;

    // ---- ranks (stable, tie -> lower index) via lane rotation ----
    int rank = 1;   // 1-based ascending rank of d
    int rr   = 0;   // 0-based descending rank of rel
#pragma unroll
    for (int o = 1; o < 32; o++) {
        const int j = (lane + o) & 31;
        const float dj = __shfl_sync(0xffffffffu, dme,   j);
        const float rj = __shfl_sync(0xffffffffu, relme, j);
        rank += (dj < dme)   || (dj == dme   && j < lane);
        rr   += (rj > relme) || (rj == relme && j < lane);
    }
    rank += (d32 < dme);          // item 32 has index 32 > lane: strict only
    rr   += (rel32 > relme);

    const int rank32 = 1 + (int)__reduce_add_sync(0xffffffffu, (unsigned)(dme <= d32));
    const int rr32   =     (int)__reduce_add_sync(0xffffffffu, (unsigned)(relme >= rel32));

    const float cme = (rank   <= KTOP) ? 1.0f / log2f((float)(rank   + 1)) : 0.0f;
    const float c32 = (rank32 <= KTOP) ? 1.0f / log2f((float)(rank32 + 1)) : 0.0f;

    // idcg = sum over items with descending-rank < KTOP of rel/log2(rr+2)
    float ic = (rr < KTOP) ? relme * __fdividef(1.0f, log2f((float)(rr + 2))) : 0.0f;
    if (lane == 0 && rr32 < KTOP) ic += rel32 * __fdividef(1.0f, log2f((float)(rr32 + 2)));
    const float idcg = warp_sum(ic);
    const float inv_idcg = (idcg > 0.0f) ? __fdividef(1.0f, idcg) : 0.0f;

    // ---- pairwise lambda: rotation covers C(32,2); o=16 double-counts -> 0.5x ----
    float acc = 0.0f;
#pragma unroll
    for (int o = 1; o <= 16; o++) {
        const int j = (lane + o) & 31;
        const float rj = __shfl_sync(0xffffffffu, relme, j);
        const float cj = __shfl_sync(0xffffffffu, cme,   j);
        const float dj = __shfl_sync(0xffffffffu, dme,   j);
        const float t  = pair_term(relme, cme, dme, rj, cj, dj, inv_idcg);
        acc += (o == 16) ? 0.5f * t : t;
    }
    // pairs (lane, 32)
    acc += pair_term(relme, cme, dme, rel32, c32, d32, inv_idcg);

    acc = warp_sum(acc);
    if (lane == 0) s_warp[w] = acc;
    __syncthreads();

    // ---- block partial (deterministic serial 8-add), then fenced last-block finish ----
    if (threadIdx.x == 0) {
        float bsum = 0.0f;
#pragma unroll
        for (int i = 0; i < WARPS_PER_BLK; i++) bsum += s_warp[i];
        g_part[blockIdx.x] = bsum;
        __threadfence();
        const int prev = atomicAdd(&g_count, 1);
        s_last = (prev == BLOCKS - 1);
    }
    __syncthreads();

    if (s_last) {
        __threadfence();
        float v = 0.0f;
        for (int i = threadIdx.x; i < BLOCKS; i += 256) v += g_part[i];
        s_fin[threadIdx.x] = v;
        __syncthreads();
#pragma unroll
        for (int o = 128; o; o >>= 1) {
            if (threadIdx.x < o) s_fin[threadIdx.x] += s_fin[threadIdx.x + o];
            __syncthreads();
        }
        if (threadIdx.x == 0) {
            out[0] = WEIGHT_ * s_fin[0] / (float)B_;
            g_count = 0;   // reset for next graph replay
        }
    }
}

extern "C" void kernel_launch(void* const* d_in, const int* in_sizes, int n_in,
                              void* d_out, int out_size)
{
    const float* anchor   = (const float*)d_in[0];
    const float* positive = (const float*)d_in[1];
    const float* negative = (const float*)d_in[2];
    const float* tree     = (const float*)d_in[3];
    const int*   aidx     = (const int*)d_in[4];
    const int*   pidx     = (const int*)d_in[5];
    const int*   nidx     = (const int*)d_in[6];

    lr_fused<<<BLOCKS, 256>>>(anchor, positive, negative, tree,
                              aidx, pidx, nidx, (float*)d_out);
}

// round 3
// speedup vs baseline: 1.5874x; 1.1583x over previous
#include <cuda_runtime.h>

constexpr int B_ = 8192;
constexpr int K_ = 32;
constexpr int D_ = 129;
constexpr int V_ = 2048;
constexpr int KTOP = 10;
constexpr float WEIGHT_ = 0.15f;
constexpr int WARPS_PER_BLK = 8;
constexpr int BLOCKS = B_ / WARPS_PER_BLK;   // 1024

__device__ float g_part[BLOCKS];
__device__ int   g_count = 0;

__device__ __forceinline__ float warp_sum(float v) {
#pragma unroll
    for (int o = 16; o; o >>= 1) v += __shfl_xor_sync(0xffffffffu, v, o);
    return v;
}
__device__ __forceinline__ float warp_max(float v) {
#pragma unroll
    for (int o = 16; o; o >>= 1) v = fmaxf(v, __shfl_xor_sync(0xffffffffu, v, o));
    return v;
}
__device__ __forceinline__ float acoshd(float x) {
    x = fmaxf(x, 1.0f + 1e-7f);
    return logf(x + sqrtf(x * x - 1.0f));
}
__device__ __forceinline__ float pair_term(float ri, float ci, float di,
                                           float rj, float cj, float dj,
                                           float inv_idcg) {
    float drel  = ri - rj;
    float delta = fabsf(drel * (ci - cj)) * inv_idcg;
    float dd    = dj - di;
    float s     = (drel > 0.0f) ? 1.0f : -1.0f;
    float x     = s * dd;
    float sig   = __fdividef(1.0f, 1.0f + __expf(-x));
    return s * delta * sig * (-dd);
}

// rounds m=8,4,2,1 of the 32-wide butterfly on a 16-register tile
__device__ __forceinline__ void bfly_tail(float q[16], int lane) {
#pragma unroll
    for (int m = 8; m >= 1; m >>= 1) {
        const bool up = (lane & m) != 0;
#pragma unroll
        for (int t = 0; t < m; t++) {
            float send = up ? q[t] : q[t + m];
            float recv = __shfl_xor_sync(0xffffffffu, send, m);
            q[t] = (up ? q[t + m] : q[t]) + recv;
        }
    }
}

__global__ void __launch_bounds__(256, 5) lr_fused(
    const float* __restrict__ anchor,
    const float* __restrict__ positive,
    const float* __restrict__ negative,
    const float* __restrict__ tree,
    const int*   __restrict__ aidx,
    const int*   __restrict__ pidx,
    const int*   __restrict__ nidx,
    float*       __restrict__ out)
{
    __shared__ float s_warp[WARPS_PER_BLK];
    __shared__ float s_fin[256];
    __shared__ bool  s_last;

    const int w    = threadIdx.x >> 5;
    const int lane = threadIdx.x & 31;
    const int b    = blockIdx.x * WARPS_PER_BLK + w;

    const float* __restrict__ arow = anchor   + (size_t)b * D_;
    const float* __restrict__ pb   = positive + (size_t)b * D_;
    const float* __restrict__ nb   = negative + (size_t)b * K_ * D_;

    // anchor regs, sign-flipped for c>=1: sum(ah_c * v_c) = -lorentz_inner
    const float ah0 = (lane == 0) ? arow[0] : -arow[lane];
    const float ah1 = -arow[lane + 32];
    const float ah2 = -arow[lane + 64];
    const float ah3 = -arow[lane + 96];
    const float a128n = -arow[128];

    float q[16];

    // ===== group 1: items 0..15 (item 0 = positive) -> lanes 0..15 =====
#pragma unroll
    for (int t = 0; t < 16; t++) {
        const float* v = (t == 0) ? pb : (nb + (t - 1) * D_);
        q[t] = fmaf(ah0, v[lane], fmaf(ah1, v[lane + 32],
               fmaf(ah2, v[lane + 64], ah3 * v[lane + 96])));
    }
    {   // round m=16: lower half owns; upper half zeroed
        const bool up = (lane & 16) != 0;
#pragma unroll
        for (int t = 0; t < 16; t++) {
            float recv = __shfl_xor_sync(0xffffffffu, q[t], 16);
            q[t] = up ? 0.0f : (q[t] + recv);
        }
    }
    bfly_tail(q, lane);
    const float r1 = q[0];              // valid on lanes 0..15: item=lane

    // ===== group 2: items 16..31 -> lanes 16..31 =====
#pragma unroll
    for (int t = 0; t < 16; t++) {
        const float* v = nb + (t + 15) * D_;
        q[t] = fmaf(ah0, v[lane], fmaf(ah1, v[lane + 32],
               fmaf(ah2, v[lane + 64], ah3 * v[lane + 96])));
    }
    {   // round m=16: upper half owns
        const bool up = (lane & 16) != 0;
#pragma unroll
        for (int t = 0; t < 16; t++) {
            float recv = __shfl_xor_sync(0xffffffffu, q[t], 16);
            q[t] = up ? (q[t] + recv) : 0.0f;
        }
    }
    bfly_tail(q, lane);
    float dsum = (lane < 16) ? r1 : q[0];   // item = lane

    // ===== item 32 =====
    {
        const float* v = nb + 31 * D_;
        float p32 = fmaf(ah0, v[lane], fmaf(ah1, v[lane + 32],
                    fmaf(ah2, v[lane + 64], ah3 * v[lane + 96])));
        q[0] = warp_sum(p32);
    }
    float s32 = q[0] + a128n * nb[31 * D_ + 128];

    // tail component (element 128) for item `lane`
    const float* rowme = (lane == 0) ? pb : (nb + (lane - 1) * D_);
    dsum += a128n * rowme[128];

    const float dme = acoshd(dsum);
    const float d32 = acoshd(s32);

    // ===== tree gather + rel =====
    const int ai = aidx[b];
    const float* __restrict__ trow = tree + (size_t)ai * V_;
    const int colme = (lane == 0) ? pidx[b] : nidx[b * K_ + lane - 1];
    const float tme = trow[colme];
    const float t32 = trow[nidx[b * K_ + 31]];

    const float maxt   = fmaxf(warp_max(tme), t32);
    const float inv_mt = __fdividef(1.0f, maxt + 1e-6f);
    const float relme  = (maxt - tme + 1e-6f) * inv_mt;
    const float rel32  = (maxt - t32 + 1e-6f) * inv_mt;

    // ===== stable ranks via lane rotation =====
    int rank = 1;   // ascending rank of d (1-based)
    int rr   = 0;   // descending rank of rel (0-based)
#pragma unroll
    for (int o = 1; o < 32; o++) {
        const int j = (lane + o) & 31;
        const float dj = __shfl_sync(0xffffffffu, dme,   j);
        const float rj = __shfl_sync(0xffffffffu, relme, j);
        rank += (dj < dme)   || (dj == dme   && j < lane);
        rr   += (rj > relme) || (rj == relme && j < lane);
    }
    rank += (d32 < dme);
    rr   += (rel32 > relme);

    const int rank32 = 1 + (int)__reduce_add_sync(0xffffffffu, (unsigned)(dme <= d32));
    const int rr32   =     (int)__reduce_add_sync(0xffffffffu, (unsigned)(relme >= rel32));

    const float cme = (rank   <= KTOP) ? 1.0f / log2f((float)(rank   + 1)) : 0.0f;
    const float c32 = (rank32 <= KTOP) ? 1.0f / log2f((float)(rank32 + 1)) : 0.0f;

    float ic = (rr < KTOP) ? relme * __fdividef(1.0f, log2f((float)(rr + 2))) : 0.0f;
    if (lane == 0 && rr32 < KTOP) ic += rel32 * __fdividef(1.0f, log2f((float)(rr32 + 2)));
    const float idcg = warp_sum(ic);
    const float inv_idcg = (idcg > 0.0f) ? __fdividef(1.0f, idcg) : 0.0f;

    // ===== pairwise lambda: rotation covers C(32,2); o=16 double-counted =====
    float acc = 0.0f;
#pragma unroll
    for (int o = 1; o <= 16; o++) {
        const int j = (lane + o) & 31;
        const float rj = __shfl_sync(0xffffffffu, relme, j);
        const float cj = __shfl_sync(0xffffffffu, cme,   j);
        const float dj = __shfl_sync(0xffffffffu, dme,   j);
        const float t  = pair_term(relme, cme, dme, rj, cj, dj, inv_idcg);
        acc += (o == 16) ? 0.5f * t : t;
    }
    acc += pair_term(relme, cme, dme, rel32, c32, d32, inv_idcg);

    acc = warp_sum(acc);
    if (lane == 0) s_warp[w] = acc;
    __syncthreads();

    if (threadIdx.x == 0) {
        float bsum = 0.0f;
#pragma unroll
        for (int i = 0; i < WARPS_PER_BLK; i++) bsum += s_warp[i];
        g_part[blockIdx.x] = bsum;
        __threadfence();
        const int prev = atomicAdd(&g_count, 1);
        s_last = (prev == BLOCKS - 1);
    }
    __syncthreads();

    if (s_last) {
        __threadfence();
        float v = 0.0f;
        for (int i = threadIdx.x; i < BLOCKS; i += 256) v += g_part[i];
        s_fin[threadIdx.x] = v;
        __syncthreads();
#pragma unroll
        for (int o = 128; o; o >>= 1) {
            if (threadIdx.x < o) s_fin[threadIdx.x] += s_fin[threadIdx.x + o];
            __syncthreads();
        }
        if (threadIdx.x == 0) {
            out[0] = WEIGHT_ * s_fin[0] / (float)B_;
            g_count = 0;
        }
    }
}

extern "C" void kernel_launch(void* const* d_in, const int* in_sizes, int n_in,
                              void* d_out, int out_size)
{
    const float* anchor   = (const float*)d_in[0];
    const float* positive = (const float*)d_in[1];
    const float* negative = (const float*)d_in[2];
    const float* tree     = (const float*)d_in[3];
    const int*   aidx     = (const int*)d_in[4];
    const int*   pidx     = (const int*)d_in[5];
    const int*   nidx     = (const int*)d_in[6];

    lr_fused<<<BLOCKS, 256>>>(anchor, positive, negative, tree,
                              aidx, pidx, nidx, (float*)d_out);
}